// round 15
// baseline (speedup 1.0000x reference)
#include <cuda_runtime.h>
#include <cuda_bf16.h>
#include <cuda_pipeline.h>
#include <math.h>

#define NB 4
#define NN 4096
#define NK 32
#define NF 128
#define EPSF 1e-8f

#define OFF_DFLAT 0
#define OFF_NUM   16384
#define OFF_SS    16388
#define OFF_PEMB  17412
#define OFF_CSUM  33796
#define OFF_RAW   34308
#define OFF_AS2   38404
#define ACC_TOTAL 38532

#define OUT_EMB   0
#define OUT_ADJ   16384
#define OUT_S     20480
#define OUT_MLOSS 544768
#define OUT_OLOSS 544769

__device__ float g_s_soft[NN * NK];
__device__ float g_w[NN];
__device__ int   g_cluster[NB * NN];
__device__ unsigned char g_cl8[NB * NN];
__device__ float g_acc[ACC_TOTAL];
__device__ float g_Rs[4u * NB * NN * NK];          // per-m-slice buckets, 8MB
__device__ __nv_bfloat16 g_Gh[(size_t)NN * NN];    // G in bf16, 32MB

// grid 128 x 128 threads; thread = (n, b) pair
__global__ void k_soft(const float* __restrict__ logits,
                       const float* __restrict__ gumbel,
                       float* __restrict__ out) {
    int tid = threadIdx.x;
    int gt = blockIdx.x * 128 + tid;
    for (int i = gt; i < ACC_TOTAL; i += 16384) g_acc[i] = 0.0f;
    int n = blockIdx.x * 32 + (tid >> 2);
    int b = tid & 3;
    float lg[32];
    const float4* lp = (const float4*)(logits + n * NK);
#pragma unroll
    for (int i = 0; i < 8; i++) {
        float4 v = lp[i];
        lg[4*i] = v.x; lg[4*i+1] = v.y; lg[4*i+2] = v.z; lg[4*i+3] = v.w;
    }
    const float t1 = 0.99995f;
    const float t2 = 0.99995f * 0.99995f;

    if (b == 0) {
        float x[32], mx = -3.4e38f;
#pragma unroll
        for (int k = 0; k < 32; k++) { x[k] = lg[k] / t2; mx = fmaxf(mx, x[k]); }
        float s = 0.0f;
#pragma unroll
        for (int k = 0; k < 32; k++) { x[k] = expf(x[k] - mx); s += x[k]; }
        float inv = 1.0f / s, w = 0.0f;
#pragma unroll
        for (int k = 0; k < 32; k++) { x[k] *= inv; w += x[k] * x[k]; }
        float4* sp = (float4*)(g_s_soft + n * NK);
#pragma unroll
        for (int i = 0; i < 8; i++)
            sp[i] = make_float4(x[4*i], x[4*i+1], x[4*i+2], x[4*i+3]);
        g_w[n] = w;
    }

    const float4* gp = (const float4*)(gumbel + ((size_t)(b * NN + n)) * NK);
    float best = -3.4e38f; int bi = 0;
#pragma unroll
    for (int i = 0; i < 8; i++) {
        float4 g = gp[i];
        float z;
        z = lg[4*i+0] / t1 + g.x; if (z > best) { best = z; bi = 4*i+0; }
        z = lg[4*i+1] / t1 + g.y; if (z > best) { best = z; bi = 4*i+1; }
        z = lg[4*i+2] / t1 + g.z; if (z > best) { best = z; bi = 4*i+2; }
        z = lg[4*i+3] / t1 + g.w; if (z > best) { best = z; bi = 4*i+3; }
    }
    g_cluster[b * NN + n] = bi;
    g_cl8[b * NN + n] = (unsigned char)bi;
    float4* op = (float4*)(out + OUT_S + ((size_t)(b * NN + n)) * NK);
#pragma unroll
    for (int i = 0; i < 8; i++) {
        float4 o;
        o.x = (4*i+0 == bi) ? 1.0f + EPSF : EPSF;
        o.y = (4*i+1 == bi) ? 1.0f + EPSF : EPSF;
        o.z = (4*i+2 == bi) ? 1.0f + EPSF : EPSF;
        o.w = (4*i+3 == bi) ? 1.0f + EPSF : EPSF;
        op[i] = o;
    }
}

// Fused: [0,1024) G gemm; [1024,1056) ss; [1056,1312) emb pooling.
__global__ void __launch_bounds__(256) k_fused(const float* __restrict__ emb) {
    __shared__ float S[8960];
    int tid = threadIdx.x;
    int bid = blockIdx.x;

    if (bid < 1024) {
        float* Sa = S;                 // 128*36
        float* SbT = S + 4608;         // 32*132
        int ti = bid >> 5, tj = bid & 31;
        for (int i = tid; i < 1024; i += 256) {
            int row = i >> 3, q = i & 7;
            float4 va = ((const float4*)(g_s_soft + (ti * 128 + row) * 32))[q];
            *(float4*)&Sa[row * 36 + q * 4] = va;
            float4 vb = ((const float4*)(g_s_soft + (tj * 128 + row) * 32))[q];
            SbT[(q * 4 + 0) * 132 + row] = vb.x;
            SbT[(q * 4 + 1) * 132 + row] = vb.y;
            SbT[(q * 4 + 2) * 132 + row] = vb.z;
            SbT[(q * 4 + 3) * 132 + row] = vb.w;
        }
        __syncthreads();
        int ry = tid >> 4, cx = tid & 15;
        unsigned long long acc2[8][4];
#pragma unroll
        for (int i = 0; i < 8; i++)
#pragma unroll
            for (int j = 0; j < 4; j++) acc2[i][j] = 0ull;
#pragma unroll 4
        for (int k = 0; k < 32; k++) {
            unsigned long long a2[8], b2[4];
#pragma unroll
            for (int i = 0; i < 8; i++) {
                float a = Sa[(ry + 16 * i) * 36 + k];
                asm("mov.b64 %0, {%1, %1};" : "=l"(a2[i]) : "f"(a));
            }
#pragma unroll
            for (int j = 0; j < 4; j++) {
                float2 bp = *(const float2*)&SbT[k * 132 + 2 * cx + 32 * j];
                asm("mov.b64 %0, {%1, %2};" : "=l"(b2[j]) : "f"(bp.x), "f"(bp.y));
            }
#pragma unroll
            for (int i = 0; i < 8; i++)
#pragma unroll
                for (int j = 0; j < 4; j++)
                    asm("fma.rn.f32x2 %0, %1, %2, %0;"
                        : "+l"(acc2[i][j]) : "l"(a2[i]), "l"(b2[j]));
        }
#pragma unroll
        for (int i = 0; i < 8; i++) {
            size_t ro = (size_t)(ti * 128 + ry + 16 * i) * NN + tj * 128 + 2 * cx;
#pragma unroll
            for (int j = 0; j < 4; j++) {
                float lo, hi;
                asm("mov.b64 {%0, %1}, %2;" : "=f"(lo), "=f"(hi) : "l"(acc2[i][j]));
                *(__nv_bfloat162*)&g_Gh[ro + 32 * j] = __floats2bfloat162_rn(lo, hi);
            }
        }
    } else if (bid < 1056) {
        float* tile = S;
        float acc[4] = {0, 0, 0, 0};
        int base_n = (bid - 1024) * 128;
        for (int ch = 0; ch < 4; ch++) {
            __syncthreads();
            const float4* src = (const float4*)(g_s_soft + (base_n + ch * 32) * NK);
            ((float4*)tile)[tid] = src[tid];
            __syncthreads();
#pragma unroll 4
            for (int r = 0; r < 32; r++) {
#pragma unroll
                for (int p = 0; p < 4; p++) {
                    int pr = tid + p * 256;
                    acc[p] += tile[r * 32 + (pr >> 5)] * tile[r * 32 + (pr & 31)];
                }
            }
        }
#pragma unroll
        for (int p = 0; p < 4; p++)
            atomicAdd(&g_acc[OFF_SS + tid + p * 256], acc[p]);
    } else {
        float* acc = S;                          // [2][32][128]
        int* cl = (int*)(S + 8192);              // [64]
        int e = bid - 1056;
        int b = e >> 6, ch = e & 63;
        int f = tid & 127, h = tid >> 7;
        for (int i = tid; i < 8192; i += 256) acc[i] = 0.0f;
        if (tid < 64) cl[tid] = g_cluster[b * NN + ch * 64 + tid];
        __syncthreads();
        float cs = 0.0f;
        int nbase = ch * 64 + h * 32;
        float* acch = acc + h * 4096;
        for (int r = 0; r < 32; r++) {
            float v = emb[((size_t)(b * NN + nbase + r)) * NF + f];
            cs += v;
            acch[cl[h * 32 + r] * 128 + f] += v;
        }
        __syncthreads();
        if (h == 0) {
#pragma unroll
            for (int k = 0; k < 32; k++)
                atomicAdd(&g_acc[OFF_PEMB + (b * 32 + k) * 128 + f],
                          acc[k * 128 + f] + acc[4096 + k * 128 + f]);
        }
        atomicAdd(&g_acc[OFF_CSUM + b * 128 + f], cs);
    }
}

// grid 4096 = 256 n-tiles x 4 m-slices x 4 batches; 128 thr.
// adj staged via cp.async 8-deep ring (self-consume, no barriers in loop);
// G register depth-2; clusters byte-packed.
__global__ void __launch_bounds__(128, 7) k_main(const float* __restrict__ adj) {
    __shared__ float R[32 * 128];       // 16KB buckets, bank = tid
    __shared__ float4 stage[8 * 128];   // 16KB adj ring
    int tid = threadIdx.x;
    int b = blockIdx.x & 3, ms = (blockIdx.x >> 2) & 3, nt = blockIdx.x >> 4;
    int w = tid >> 5, r = (tid >> 3) & 3, mg = tid & 7;
    int n = nt * 16 + w * 4 + r;
    int mbase = ms * 1024;

    for (int i = tid; i < 4096; i += 128) R[i] = 0.0f;
    __syncthreads();

    float mc = 0, rs = 0;
    const uint2* Gp = (const uint2*)(g_Gh + (size_t)n * NN + mbase);
    const float4* Ap =
        (const float4*)(adj + ((size_t)(b * NN + n)) * NN + mbase);
    const unsigned* Cp = (const unsigned*)(g_cl8 + b * NN + mbase);

#pragma unroll
    for (int s = 0; s < 8; s++) {
        __pipeline_memcpy_async(&stage[s * 128 + tid], &Ap[s * 8 + mg], 16);
        __pipeline_commit();
    }
    uint2 gb[2];
    gb[0] = Gp[mg]; gb[1] = Gp[8 + mg];
    unsigned cc = Cp[mg];

#pragma unroll 4
    for (int it = 0; it < 32; it++) {
        __pipeline_wait_prior(7);
        float4 a = stage[(it & 7) * 128 + tid];
        if (it < 24)
            __pipeline_memcpy_async(&stage[(it & 7) * 128 + tid],
                                    &Ap[(it + 8) * 8 + mg], 16);
        __pipeline_commit();
        uint2 gg = gb[it & 1];
        unsigned c = cc;
        if (it < 30) gb[it & 1] = Gp[(it + 2) * 8 + mg];
        if (it < 31) cc = Cp[(it + 1) * 8 + mg];
        float2 glo = __bfloat1622float2(*(__nv_bfloat162*)&gg.x);
        float2 ghi = __bfloat1622float2(*(__nv_bfloat162*)&gg.y);
        mc += a.x * glo.x + a.y * glo.y + a.z * ghi.x + a.w * ghi.y;
        rs += (a.x + a.y) + (a.z + a.w);
        float* R0 = R + tid;
        R0[(c & 31u) << 7] += a.x;
        R0[((c >> 8) & 31u) << 7] += a.y;
        R0[((c >> 16) & 31u) << 7] += a.z;
        R0[((c >> 24) & 31u) << 7] += a.w;
    }

    const unsigned F = 0xffffffffu;
    {
        float v = rs;
        v += __shfl_xor_sync(F, v, 1);
        v += __shfl_xor_sync(F, v, 2);
        v += __shfl_xor_sync(F, v, 4);
        if (mg == 0) atomicAdd(&g_acc[OFF_DFLAT + b * NN + n], v);
        float m = mc;
#pragma unroll
        for (int o = 16; o > 0; o >>= 1) m += __shfl_down_sync(F, m, o);
        if ((tid & 31) == 0) atomicAdd(&g_acc[OFF_NUM + b], m);

        float vc[32];
#pragma unroll
        for (int c2 = 0; c2 < 32; c2++) {
            float x = R[(c2 << 7) + tid];
            x += __shfl_xor_sync(F, x, 1);
            x += __shfl_xor_sync(F, x, 2);
            x += __shfl_xor_sync(F, x, 4);
            vc[c2] = x;
        }
        if (mg == 0) {
            float4* dst = (float4*)(g_Rs + ((size_t)((ms * 4 + b) * NN + n)) * 32);
#pragma unroll
            for (int i = 0; i < 8; i++)
                dst[i] = make_float4(vc[4*i], vc[4*i+1], vc[4*i+2], vc[4*i+3]);
        }
    }
}

// grid 512 = B x 128 chunks of 32 rows; 256 thr = 8 warps
__global__ void k_oadj() {
    __shared__ float acc[8 * 32 * 32];
    __shared__ float s2[8 * 32];
    int tid = threadIdx.x, w = tid >> 5, l = tid & 31;
    int b = blockIdx.x >> 7, ch = blockIdx.x & 127;
    for (int i = tid; i < 8 * 32 * 32; i += 256) acc[i] = 0.0f;
    __syncthreads();
    float s2l = 0.0f;
    for (int r = w; r < 32; r += 8) {
        int n = ch * 32 + r;
        float as2 = EPSF * g_acc[OFF_DFLAT + b * NN + n];
#pragma unroll
        for (int s = 0; s < 4; s++)
            as2 += g_Rs[((size_t)((s * 4 + b) * NN + n)) * 32 + l];
        int c = g_cluster[b * NN + n];
        acc[(w * 32 + c) * 32 + l] += as2;
        s2l += as2;
    }
    s2[w * 32 + l] = s2l;
    __syncthreads();
#pragma unroll
    for (int p = 0; p < 4; p++) {
        int pr = tid + p * 256;
        float s = 0.0f;
#pragma unroll
        for (int ww = 0; ww < 8; ww++) s += acc[ww * 1024 + pr];
        atomicAdd(&g_acc[OFF_RAW + b * 1024 + pr], s);
    }
    if (tid < 32) {
        float s = 0.0f;
#pragma unroll
        for (int ww = 0; ww < 8; ww++) s += s2[ww * 32 + tid];
        atomicAdd(&g_acc[OFF_AS2 + b * 32 + tid], s);
    }
}

__global__ void k_fin(float* __restrict__ out) {
    __shared__ float red[256];
    __shared__ float adjb[4096];
    __shared__ float dbk[128];
    __shared__ float fro_s;
    int tid = threadIdx.x;
    const unsigned F = 0xffffffffu;

    float den[4] = {0, 0, 0, 0};
    for (int i = tid; i < NN; i += 256) {
        float wv = g_w[i];
#pragma unroll
        for (int b = 0; b < 4; b++) den[b] += g_acc[OFF_DFLAT + b * NN + i] * wv;
    }
#pragma unroll
    for (int b = 0; b < 4; b++) {
        float v = den[b];
#pragma unroll
        for (int o = 16; o > 0; o >>= 1) v += __shfl_down_sync(F, v, o);
        if ((tid & 31) == 0) red[(tid >> 5) * 4 + b] = v;
    }
    __syncthreads();
    if (tid < 32) {
        float v = red[tid];
        v += __shfl_down_sync(F, v, 16);
        v += __shfl_down_sync(F, v, 8);
        v += __shfl_down_sync(F, v, 4);
        if (tid < 4) red[64 + tid] = g_acc[OFF_NUM + tid] / v;
    }
    __syncthreads();
    if (tid == 0)
        out[OUT_MLOSS] = -0.25f * (red[64] + red[65] + red[66] + red[67]);
    __syncthreads();

    float f2 = 0.0f;
    for (int i = tid; i < 1024; i += 256) {
        float v = g_acc[OFF_SS + i]; f2 += v * v;
    }
    red[tid] = f2; __syncthreads();
    for (int s = 128; s > 0; s >>= 1) {
        if (tid < s) red[tid] += red[tid + s];
        __syncthreads();
    }
    if (tid == 0) fro_s = sqrtf(red[0]);
    __syncthreads();
    float invf = 1.0f / fro_s;
    const float isq = 0.17677669529663687f;
    float o2 = 0.0f;
    for (int i = tid; i < 1024; i += 256) {
        float v = g_acc[OFF_SS + i] * invf;
        if ((i >> 5) == (i & 31)) v -= isq;
        o2 += v * v;
    }
    red[tid] = o2; __syncthreads();
    for (int s = 128; s > 0; s >>= 1) {
        if (tid < s) red[tid] += red[tid + s];
        __syncthreads();
    }
    if (tid == 0) out[OUT_OLOSS] = sqrtf(red[0]);

    for (int i = tid; i < 16384; i += 256) {
        int b = i >> 12, f = i & 127;
        out[OUT_EMB + i] = g_acc[OFF_PEMB + i] + EPSF * g_acc[OFF_CSUM + b * 128 + f];
    }

    for (int i = tid; i < 4096; i += 256) {
        int b = i >> 10, k = (i >> 5) & 31, l = i & 31;
        float v = (k == l) ? 0.0f
                 : g_acc[OFF_RAW + i] + EPSF * g_acc[OFF_AS2 + b * 32 + l];
        adjb[i] = v;
    }
    __syncthreads();
    if (tid < 128) {
        float s = 0.0f;
#pragma unroll
        for (int l = 0; l < 32; l++) s += adjb[tid * 32 + l];
        dbk[tid] = sqrtf(s) + EPSF;
    }
    __syncthreads();
    for (int i = tid; i < 4096; i += 256) {
        int b = i >> 10, k = (i >> 5) & 31, l = i & 31;
        out[OUT_ADJ + i] = adjb[i] / (dbk[b * 32 + k] * dbk[b * 32 + l]);
    }
}

extern "C" void kernel_launch(void* const* d_in, const int* in_sizes, int n_in,
                              void* d_out, int out_size) {
    const float* emb    = (const float*)d_in[0];
    const float* adj    = (const float*)d_in[1];
    const float* logits = (const float*)d_in[2];
    const float* gumbel = (const float*)d_in[3];
    float* out = (float*)d_out;
    k_soft<<<128, 128>>>(logits, gumbel, out);
    k_fused<<<1312, 256>>>(emb);
    k_main<<<4096, 128>>>(adj);
    k_oadj<<<512, 256>>>();
    k_fin<<<1, 256>>>(out);
}